// round 1
// baseline (speedup 1.0000x reference)
#include <cuda_runtime.h>
#include <cstdint>

// Problem constants
#define Bb 8
#define Cc 64
#define Nn 500
#define Tt 12
#define Hh 4
#define Ff 64
#define Ss (Bb * Tt)   // 96 slices (b,t)
#define HF (Hh * Ff)   // 256
#define MAXD 128
#define ALPHAc 0.05f
#define LEAKc 0.2f

// ---------------- scratch (device globals; no allocation) ----------------
__device__ float g_xT[Ss * Nn * Cc];            // [s,n,c]
__device__ float g_h1T[Ss * Nn * Cc];
__device__ float g_h2T[Ss * Nn * Cc];
__device__ float g_Wh[(size_t)Ss * Nn * HF];    // [s,n,h*F+f]
__device__ float g_hpr[(size_t)Ss * Nn * HF];   // [s,n,h*F+f]
__device__ float g_e1[Ss * Hh * Nn];            // [(s*H+h)*N + n]
__device__ float g_e2[Ss * Hh * Nn];
__device__ float g_Wcat[Cc * HF];               // [c, h*F+f]
__device__ float g_WgT[HF * Cc];                // [hf, o]
__device__ float g_WmT[3 * Cc * Cc];            // [c_global, o]
__device__ int   g_cnt[Nn];
__device__ int   g_nbr[Nn * MAXD];

// ---------------- neighbor list from dense adjacency ----------------
__global__ void build_nbr(const float* __restrict__ adj) {
    int n = blockIdx.x * blockDim.x + threadIdx.x;
    if (n >= Nn) return;
    int c = 0;
    for (int m = 0; m < Nn; ++m) {
        if (adj[n * Nn + m] > 0.f || m == n) {
            if (c < MAXD) g_nbr[n * MAXD + c] = m;
            ++c;
        }
    }
    g_cnt[n] = c < MAXD ? c : MAXD;
}

// ---------------- weight re-layouts ----------------
__global__ void prep_weights(const float* __restrict__ W,
                             const float* __restrict__ Wg,
                             const float* __restrict__ Wm) {
    int i = blockIdx.x * blockDim.x + threadIdx.x;
    if (i < Hh * Cc * Ff) {  // Wcat[c, h*F+f] = W[h,c,f]
        int f = i % Ff; int rest = i / Ff;
        int c = rest % Cc; int h = rest / Cc;
        g_Wcat[c * HF + h * Ff + f] = W[(h * Cc + c) * Ff + f];
    }
    if (i < HF * Cc) {       // WgT[hf, o] = Wg[o, hf]
        int o = i % Cc; int hf = i / Cc;
        g_WgT[hf * Cc + o] = Wg[o * HF + hf];
    }
    if (i < 3 * Cc * Cc) {   // WmT[c, o] = Wm[o, c]
        int o = i % Cc; int c = i / Cc;
        g_WmT[c * Cc + o] = Wm[o * (3 * Cc) + c];
    }
}

// ---------------- input transpose: x[b,c,n,t] -> xT[s,n,c], s=b*T+t ----------------
__global__ void transpose_in(const float* __restrict__ x, float* __restrict__ xT) {
    int idx = blockIdx.x * blockDim.x + threadIdx.x;
    if (idx >= Ss * Nn * Cc) return;
    int c = idx & 63;
    int rest = idx >> 6;
    int n = rest % Nn;
    int s = rest / Nn;
    int b = s / Tt, t = s % Tt;
    xT[idx] = x[(((size_t)b * Cc + c) * Nn + n) * Tt + t];
}

// ---------------- per-slice GEMM: C[s] = A[s](M,K) @ Bm(K,Nc) ----------------
// mode 0: plain store. mode 1: out = ALPHA*resid + (1-ALPHA)*(acc + bias)
__global__ void gemm_slice_kernel(const float* __restrict__ A,
                                  const float* __restrict__ Bm,
                                  float* __restrict__ Cm,
                                  const float* __restrict__ bias,
                                  const float* __restrict__ resid,
                                  int M, int K, int Nc, int mode) {
    __shared__ float As[64][65];
    __shared__ float Bs[64][68];
    const int s = blockIdx.x;
    const int r0 = blockIdx.y * 64;
    const int c0 = blockIdx.z * 64;
    const float* Asl = A + (size_t)s * M * K;
    const int tid = threadIdx.x;
    const int tx = tid & 15, ty = tid >> 4;
    float acc[4][4] = {};
    for (int kb = 0; kb < K; kb += 64) {
        #pragma unroll 4
        for (int i = tid; i < 64 * 64; i += 256) {
            int r = i >> 6, k = i & 63;
            int row = r0 + r;
            As[r][k] = (row < M) ? Asl[(size_t)row * K + kb + k] : 0.f;
        }
        #pragma unroll 4
        for (int i = tid; i < 64 * 64; i += 256) {
            int k = i >> 6, c = i & 63;
            Bs[k][c] = Bm[(size_t)(kb + k) * Nc + c0 + c];
        }
        __syncthreads();
        #pragma unroll
        for (int k = 0; k < 64; ++k) {
            float a[4];
            #pragma unroll
            for (int i = 0; i < 4; ++i) a[i] = As[ty * 4 + i][k];
            float4 b4 = *(const float4*)&Bs[k][tx * 4];
            float b[4] = {b4.x, b4.y, b4.z, b4.w};
            #pragma unroll
            for (int i = 0; i < 4; ++i)
                #pragma unroll
                for (int j = 0; j < 4; ++j)
                    acc[i][j] = fmaf(a[i], b[j], acc[i][j]);
        }
        __syncthreads();
    }
    #pragma unroll
    for (int i = 0; i < 4; ++i) {
        int row = r0 + ty * 4 + i;
        if (row >= M) continue;
        #pragma unroll
        for (int j = 0; j < 4; ++j) {
            int col = c0 + tx * 4 + j;
            size_t oidx = (size_t)s * M * Nc + (size_t)row * Nc + col;
            float v = acc[i][j];
            if (mode == 1)
                v = ALPHAc * resid[oidx] + (1.f - ALPHAc) * (v + bias[col]);
            Cm[oidx] = v;
        }
    }
}

// ---------------- e1/e2: per-(s,h,n) dot of Wh row with a1/a2 ----------------
__global__ void compute_e(const float* __restrict__ Wh,
                          const float* __restrict__ a1,
                          const float* __restrict__ a2,
                          float* __restrict__ e1, float* __restrict__ e2) {
    int warp = (blockIdx.x * blockDim.x + threadIdx.x) >> 5;
    int lane = threadIdx.x & 31;
    if (warp >= Ss * Hh * Nn) return;
    int n = warp % Nn;
    int sh = warp / Nn;
    int h = sh % Hh;
    int s = sh / Hh;
    const float2 w = *(const float2*)&Wh[((size_t)(s * Nn + n)) * HF + h * Ff + 2 * lane];
    float2 A1 = *(const float2*)&a1[h * Ff + 2 * lane];
    float2 A2 = *(const float2*)&a2[h * Ff + 2 * lane];
    float v1 = w.x * A1.x + w.y * A1.y;
    float v2 = w.x * A2.x + w.y * A2.y;
    #pragma unroll
    for (int o = 16; o; o >>= 1) {
        v1 += __shfl_xor_sync(0xffffffffu, v1, o);
        v2 += __shfl_xor_sync(0xffffffffu, v2, o);
    }
    if (lane == 0) { e1[warp] = v1; e2[warp] = v2; }
}

// ---------------- sparse attention + aggregation (warp per (s,h,n)) ----------------
__global__ void attn_agg(const float* __restrict__ Wh,
                         const float* __restrict__ e1,
                         const float* __restrict__ e2,
                         float* __restrict__ hpr) {
    int warp = (blockIdx.x * blockDim.x + threadIdx.x) >> 5;
    int lane = threadIdx.x & 31;
    if (warp >= Ss * Hh * Nn) return;
    int n = warp % Nn;
    int sh = warp / Nn;
    int h = sh % Hh;
    int s = sh / Hh;

    const int cnt = g_cnt[n];
    const float e1v = e1[warp];
    const float* e2row = e2 + (size_t)sh * Nn;

    float ev[4];
    int mv[4];
    float mx = -1e30f;
    #pragma unroll
    for (int k = 0; k < 4; ++k) {
        int j = k * 32 + lane;
        float e = -1e30f; int m = 0;
        if (j < cnt) {
            m = g_nbr[n * MAXD + j];
            float t = e1v + e2row[m];
            e = t > 0.f ? t : LEAKc * t;
        }
        ev[k] = e; mv[k] = m;
        mx = fmaxf(mx, e);
    }
    #pragma unroll
    for (int o = 16; o; o >>= 1) mx = fmaxf(mx, __shfl_xor_sync(0xffffffffu, mx, o));
    float sum = 0.f;
    #pragma unroll
    for (int k = 0; k < 4; ++k) {
        int j = k * 32 + lane;
        float w = (j < cnt) ? __expf(ev[k] - mx) : 0.f;
        ev[k] = w;
        sum += w;
    }
    #pragma unroll
    for (int o = 16; o; o >>= 1) sum += __shfl_xor_sync(0xffffffffu, sum, o);
    const float inv = 1.f / sum;

    const float* Whb = Wh + h * Ff + 2 * lane;
    float2 acc = make_float2(0.f, 0.f);
    #pragma unroll 1
    for (int k = 0; k < 4; ++k) {
        if (k * 32 >= cnt) break;
        #pragma unroll
        for (int jj = 0; jj < 32; ++jj) {
            if (k * 32 + jj >= cnt) break;
            float w = __shfl_sync(0xffffffffu, ev[k], jj) * inv;
            int m = __shfl_sync(0xffffffffu, mv[k], jj);
            const float2 whv = *(const float2*)(Whb + (size_t)(s * Nn + m) * HF);
            acc.x = fmaf(w, whv.x, acc.x);
            acc.y = fmaf(w, whv.y, acc.y);
        }
    }
    float2 o2;
    o2.x = acc.x > 0.f ? acc.x : (__expf(acc.x) - 1.f);
    o2.y = acc.y > 0.f ? acc.y : (__expf(acc.y) - 1.f);
    *(float2*)&hpr[((size_t)(s * Nn + n)) * HF + h * Ff + 2 * lane] = o2;
}

// ---------------- final: out[b,o,n,t] = bm[o] + Wm @ [x; h1; h2] ----------------
__global__ void final_out(const float* __restrict__ xT,
                          const float* __restrict__ h1,
                          const float* __restrict__ h2,
                          const float* __restrict__ bm,
                          float* __restrict__ out) {
    __shared__ float sX[16][64], sH1[16][64], sH2[16][64];
    const int s = blockIdx.x;
    const int n0 = blockIdx.y * 16;
    const int tid = threadIdx.x;
    for (int i = tid; i < 16 * 64; i += 256) {
        int nl = i >> 6, c = i & 63;
        int n = n0 + nl;
        size_t idx = ((size_t)s * Nn + (n < Nn ? n : 0)) * Cc + c;
        sX[nl][c]  = (n < Nn) ? xT[idx] : 0.f;
        sH1[nl][c] = (n < Nn) ? h1[idx] : 0.f;
        sH2[nl][c] = (n < Nn) ? h2[idx] : 0.f;
    }
    __syncthreads();
    const int o = tid & 63, ng = tid >> 6;
    float acc[4] = {0.f, 0.f, 0.f, 0.f};
    #pragma unroll 4
    for (int c = 0; c < 64; ++c) {
        float w0 = g_WmT[c * Cc + o];
        float w1 = g_WmT[(64 + c) * Cc + o];
        float w2 = g_WmT[(128 + c) * Cc + o];
        #pragma unroll
        for (int r = 0; r < 4; ++r) {
            int nl = ng + r * 4;
            acc[r] = fmaf(w0, sX[nl][c], fmaf(w1, sH1[nl][c], fmaf(w2, sH2[nl][c], acc[r])));
        }
    }
    const int b = s / Tt, t = s % Tt;
    const float bias = bm[o];
    #pragma unroll
    for (int r = 0; r < 4; ++r) {
        int n = n0 + ng + r * 4;
        if (n < Nn)
            out[(((size_t)b * Cc + o) * Nn + n) * Tt + t] = acc[r] + bias;
    }
}

// ---------------- launch ----------------
extern "C" void kernel_launch(void* const* d_in, const int* in_sizes, int n_in,
                              void* d_out, int out_size) {
    const float* x   = (const float*)d_in[0];
    const float* adj = (const float*)d_in[1];
    const float* W   = (const float*)d_in[2];
    const float* a1  = (const float*)d_in[3];
    const float* a2  = (const float*)d_in[4];
    const float* Wg  = (const float*)d_in[5];
    const float* bg  = (const float*)d_in[6];
    const float* Wm  = (const float*)d_in[7];
    const float* bm  = (const float*)d_in[8];
    float* out = (float*)d_out;

    float *xT, *h1T, *h2T, *Wh, *hpr, *e1, *e2, *Wcat, *WgT;
    cudaGetSymbolAddress((void**)&xT,  g_xT);
    cudaGetSymbolAddress((void**)&h1T, g_h1T);
    cudaGetSymbolAddress((void**)&h2T, g_h2T);
    cudaGetSymbolAddress((void**)&Wh,  g_Wh);
    cudaGetSymbolAddress((void**)&hpr, g_hpr);
    cudaGetSymbolAddress((void**)&e1,  g_e1);
    cudaGetSymbolAddress((void**)&e2,  g_e2);
    cudaGetSymbolAddress((void**)&Wcat, g_Wcat);
    cudaGetSymbolAddress((void**)&WgT,  g_WgT);

    build_nbr<<<(Nn + 127) / 128, 128>>>(adj);
    prep_weights<<<64, 256>>>(W, Wg, Wm);
    transpose_in<<<(Ss * Nn * Cc + 255) / 256, 256>>>(x, xT);

    const int nwarps = Ss * Hh * Nn;               // 192000
    const int nblk = (nwarps * 32 + 255) / 256;    // 24000

    const float* hin = xT;
    float* hb[2] = {h1T, h2T};
    for (int it = 0; it < 2; ++it) {
        // Wh[s,n,hf] = hin[s,n,c] @ Wcat[c,hf]
        gemm_slice_kernel<<<dim3(Ss, (Nn + 63) / 64, HF / 64), 256>>>(
            hin, Wcat, Wh, nullptr, nullptr, Nn, Cc, HF, 0);
        compute_e<<<nblk, 256>>>(Wh, a1, a2, e1, e2);
        attn_agg<<<nblk, 256>>>(Wh, e1, e2, hpr);
        // h_next = ALPHA*x + (1-ALPHA)*(hpr @ WgT + bg)
        gemm_slice_kernel<<<dim3(Ss, (Nn + 63) / 64, Cc / 64), 256>>>(
            hpr, WgT, hb[it], bg, xT, Nn, HF, Cc, 1);
        hin = hb[it];
    }
    final_out<<<dim3(Ss, (Nn + 15) / 16), 256>>>(xT, h1T, h2T, bm, out);
}

// round 2
// speedup vs baseline: 1.3978x; 1.3978x over previous
#include <cuda_runtime.h>
#include <cuda_fp16.h>
#include <cstdint>

// Problem constants
#define Bb 8
#define Cc 64
#define Nn 500
#define Tt 12
#define Hh 4
#define Ff 64
#define Ss (Bb * Tt)   // 96 slices (b,t)
#define HF (Hh * Ff)   // 256
#define MAXD 128
#define ALPHAc 0.05f
#define LEAKc 0.2f

// ---------------- scratch (device globals; no allocation) ----------------
__device__ float   g_xT[Ss * Nn * Cc];                 // [s,n,c]
__device__ float   g_h1T[Ss * Nn * Cc];
__device__ float   g_h2T[Ss * Nn * Cc];
__device__ __half2 g_Wh16[(size_t)Ss * Nn * (HF / 2)]; // [s,n,hf/2] fp16 pairs
__device__ float   g_hpr[(size_t)Ss * Nn * HF];        // [s,n,h*F+f] fp32
__device__ float   g_e1[Ss * Hh * Nn];                 // [(s*H+h)*N + n]
__device__ float   g_e2[Ss * Hh * Nn];
__device__ float   g_Wcat[Cc * HF];                    // [c, h*F+f]
__device__ float   g_WgT[HF * Cc];                     // [hf, o]
__device__ float   g_WmT[3 * Cc * Cc];                 // [c_global, o]
__device__ int     g_cnt[Nn];
__device__ int     g_nbr[Nn * MAXD];

// ---------------- neighbor list (deterministic warp scan, warp per row) ----------------
__global__ void build_nbr(const float* __restrict__ adj) {
    int warp = threadIdx.x >> 5;
    int lane = threadIdx.x & 31;
    int n = blockIdx.x * 4 + warp;
    if (n >= Nn) return;
    int base = 0;
    for (int m0 = 0; m0 < 512; m0 += 32) {
        int m = m0 + lane;
        bool p = (m < Nn) && (adj[n * Nn + m] > 0.f || m == n);
        unsigned mask = __ballot_sync(0xffffffffu, p);
        if (p) {
            int r = __popc(mask & ((1u << lane) - 1));
            if (base + r < MAXD) g_nbr[n * MAXD + base + r] = m;
        }
        base += __popc(mask);
    }
    if (lane == 0) g_cnt[n] = base < MAXD ? base : MAXD;
}

// ---------------- weight re-layouts ----------------
__global__ void prep_weights(const float* __restrict__ W,
                             const float* __restrict__ Wg,
                             const float* __restrict__ Wm) {
    int i = blockIdx.x * blockDim.x + threadIdx.x;
    if (i < Hh * Cc * Ff) {  // Wcat[c, h*F+f] = W[h,c,f]
        int f = i % Ff; int rest = i / Ff;
        int c = rest % Cc; int h = rest / Cc;
        g_Wcat[c * HF + h * Ff + f] = W[(h * Cc + c) * Ff + f];
    }
    if (i < HF * Cc) {       // WgT[hf, o] = Wg[o, hf]
        int o = i % Cc; int hf = i / Cc;
        g_WgT[hf * Cc + o] = Wg[o * HF + hf];
    }
    if (i < 3 * Cc * Cc) {   // WmT[c, o] = Wm[o, c]
        int o = i % Cc; int c = i / Cc;
        g_WmT[c * Cc + o] = Wm[o * (3 * Cc) + c];
    }
}

// ---------------- tiled input transpose: x[b,c,n,t] -> xT[s,n,c] ----------------
// block: (n-tile 16, c-tile 16, b), 192 threads; both phases coalesced
__global__ void transpose_in(const float* __restrict__ x, float* __restrict__ xT) {
    __shared__ float sm[16][193];
    const int b = blockIdx.z, c0 = blockIdx.y * 16, n0 = blockIdx.x * 16;
    const int tt_ = threadIdx.x;            // 0..191
    const int ni_l = tt_ / 12, tl = tt_ % 12;
    const int n_l = n0 + ni_l;
    #pragma unroll
    for (int ci = 0; ci < 16; ++ci) {
        float v = 0.f;
        if (n_l < Nn)
            v = x[(((size_t)b * Cc + c0 + ci) * Nn + n_l) * Tt + tl];
        sm[ci][tt_] = v;
    }
    __syncthreads();
    #pragma unroll
    for (int rep = 0; rep < 16; ++rep) {
        int idx = rep * 192 + tt_;          // 0..3071
        int ci = idx & 15;
        int rest = idx >> 4;                // ni*12 + t
        int ni = rest / 12, t = rest % 12;
        int n = n0 + ni;
        if (n < Nn)
            xT[(((size_t)(b * Tt + t) * Nn) + n) * Cc + c0 + ci] = sm[ci][rest];
    }
}

// ---------------- projection GEMM + fused e1/e2 + fp16 Wh store ----------------
// grid (Ss, ceil(N/64), H). C_block = A[s](64 rows, K=64) @ Wcat[:, h*64:h*64+64]
__global__ void gemm_proj(const float* __restrict__ A,
                          const float* __restrict__ a1,
                          const float* __restrict__ a2) {
    __shared__ float As[64][65];
    __shared__ float Bs[64][68];
    const int s = blockIdx.x;
    const int r0 = blockIdx.y * 64;
    const int h = blockIdx.z;
    const int c0 = h * 64;
    const float* Asl = A + (size_t)s * Nn * Cc;
    const int tid = threadIdx.x;
    const int tx = tid & 15, ty = tid >> 4;

    #pragma unroll 4
    for (int i = tid; i < 64 * 64; i += 256) {
        int r = i >> 6, k = i & 63;
        int row = r0 + r;
        As[r][k] = (row < Nn) ? Asl[(size_t)row * Cc + k] : 0.f;
    }
    #pragma unroll 4
    for (int i = tid; i < 64 * 64; i += 256) {
        int k = i >> 6, c = i & 63;
        Bs[k][c] = g_Wcat[k * HF + c0 + c];
    }
    __syncthreads();

    float acc[4][4] = {};
    #pragma unroll
    for (int k = 0; k < 64; ++k) {
        float a[4];
        #pragma unroll
        for (int i = 0; i < 4; ++i) a[i] = As[ty * 4 + i][k];
        float4 b4 = *(const float4*)&Bs[k][tx * 4];
        float b[4] = {b4.x, b4.y, b4.z, b4.w};
        #pragma unroll
        for (int i = 0; i < 4; ++i)
            #pragma unroll
            for (int j = 0; j < 4; ++j)
                acc[i][j] = fmaf(a[i], b[j], acc[i][j]);
    }

    // fused e1/e2: e[i] = sum over 64 cols of acc*a-vec, reduce across 16 tx lanes
    float4 A1 = *(const float4*)&a1[c0 + tx * 4];
    float4 A2 = *(const float4*)&a2[c0 + tx * 4];
    float p1[4], p2[4];
    #pragma unroll
    for (int i = 0; i < 4; ++i) {
        p1[i] = acc[i][0] * A1.x + acc[i][1] * A1.y + acc[i][2] * A1.z + acc[i][3] * A1.w;
        p2[i] = acc[i][0] * A2.x + acc[i][1] * A2.y + acc[i][2] * A2.z + acc[i][3] * A2.w;
    }
    #pragma unroll
    for (int o = 1; o < 16; o <<= 1) {
        #pragma unroll
        for (int i = 0; i < 4; ++i) {
            p1[i] += __shfl_xor_sync(0xffffffffu, p1[i], o);
            p2[i] += __shfl_xor_sync(0xffffffffu, p2[i], o);
        }
    }
    const int sh = s * Hh + h;
    if (tx == 0) {
        #pragma unroll
        for (int i = 0; i < 4; ++i) {
            int row = r0 + ty * 4 + i;
            if (row < Nn) {
                g_e1[sh * Nn + row] = p1[i];
                g_e2[sh * Nn + row] = p2[i];
            }
        }
    }

    // fp16 store of Wh
    #pragma unroll
    for (int i = 0; i < 4; ++i) {
        int row = r0 + ty * 4 + i;
        if (row >= Nn) continue;
        size_t base = ((size_t)s * Nn + row) * (HF / 2) + (c0 >> 1) + tx * 2;
        g_Wh16[base]     = __floats2half2_rn(acc[i][0], acc[i][1]);
        g_Wh16[base + 1] = __floats2half2_rn(acc[i][2], acc[i][3]);
    }
}

// ---------------- attention softmax + aggregation: block per (n,s), 128 thr ----------------
__global__ void attn_agg(float* __restrict__ hpr) {
    const int n = blockIdx.x, s = blockIdx.y;
    const int t = threadIdx.x;        // 0..127 -> hf pair 2t,2t+1
    const int h = t >> 5, lane = t & 31;
    __shared__ int snbr[MAXD];
    __shared__ float sw[Hh][MAXD];

    const int cnt = min(g_cnt[n], MAXD);
    for (int j = t; j < cnt; j += 128) snbr[j] = g_nbr[n * MAXD + j];
    __syncthreads();

    // phase 1: per-warp softmax for head h
    const int sh = s * Hh + h;
    const float e1v = g_e1[sh * Nn + n];
    const float* e2r = g_e2 + (size_t)sh * Nn;
    float ev[4];
    float mx = -1e30f;
    #pragma unroll
    for (int k = 0; k < 4; ++k) {
        int j = k * 32 + lane;
        float e = -1e30f;
        if (j < cnt) {
            float tv = e1v + e2r[snbr[j]];
            e = tv > 0.f ? tv : LEAKc * tv;
        }
        ev[k] = e;
        mx = fmaxf(mx, e);
    }
    #pragma unroll
    for (int o = 16; o; o >>= 1) mx = fmaxf(mx, __shfl_xor_sync(0xffffffffu, mx, o));
    float sum = 0.f;
    #pragma unroll
    for (int k = 0; k < 4; ++k) {
        float w = (k * 32 + lane < cnt) ? __expf(ev[k] - mx) : 0.f;
        ev[k] = w;
        sum += w;
    }
    #pragma unroll
    for (int o = 16; o; o >>= 1) sum += __shfl_xor_sync(0xffffffffu, sum, o);
    const float inv = 1.f / sum;
    #pragma unroll
    for (int k = 0; k < 4; ++k) {
        int j = k * 32 + lane;
        if (j < cnt) sw[h][j] = ev[k] * inv;
    }
    __syncthreads();

    // phase 2: coalesced fp16 gather, unrolled x4 for MLP
    const size_t rowB = (size_t)s * Nn;
    const float* swh = sw[h];
    float ax = 0.f, ay = 0.f;
    int j = 0;
    for (; j + 4 <= cnt; j += 4) {
        int m0 = snbr[j], m1 = snbr[j + 1], m2 = snbr[j + 2], m3 = snbr[j + 3];
        float w0 = swh[j], w1 = swh[j + 1], w2 = swh[j + 2], w3 = swh[j + 3];
        float2 f0 = __half22float2(g_Wh16[(rowB + m0) * (HF / 2) + t]);
        float2 f1 = __half22float2(g_Wh16[(rowB + m1) * (HF / 2) + t]);
        float2 f2 = __half22float2(g_Wh16[(rowB + m2) * (HF / 2) + t]);
        float2 f3 = __half22float2(g_Wh16[(rowB + m3) * (HF / 2) + t]);
        ax = fmaf(w0, f0.x, fmaf(w1, f1.x, fmaf(w2, f2.x, fmaf(w3, f3.x, ax))));
        ay = fmaf(w0, f0.y, fmaf(w1, f1.y, fmaf(w2, f2.y, fmaf(w3, f3.y, ay))));
    }
    for (; j < cnt; ++j) {
        float w = swh[j];
        float2 f = __half22float2(g_Wh16[(rowB + snbr[j]) * (HF / 2) + t]);
        ax = fmaf(w, f.x, ax);
        ay = fmaf(w, f.y, ay);
    }
    float2 o2;
    o2.x = ax > 0.f ? ax : (__expf(ax) - 1.f);
    o2.y = ay > 0.f ? ay : (__expf(ay) - 1.f);
    ((float2*)hpr)[(rowB + n) * (HF / 2) + t] = o2;
}

// ---------------- mix GEMM: h_next = ALPHA*x + (1-ALPHA)*(hpr @ WgT + bg) ----------------
__global__ void gemm_mix(const float* __restrict__ A,
                         const float* __restrict__ bias,
                         const float* __restrict__ resid,
                         float* __restrict__ Cm) {
    __shared__ float As[64][65];
    __shared__ float Bs[64][68];
    const int s = blockIdx.x;
    const int r0 = blockIdx.y * 64;
    const float* Asl = A + (size_t)s * Nn * HF;
    const int tid = threadIdx.x;
    const int tx = tid & 15, ty = tid >> 4;
    float acc[4][4] = {};
    for (int kb = 0; kb < HF; kb += 64) {
        #pragma unroll 4
        for (int i = tid; i < 64 * 64; i += 256) {
            int r = i >> 6, k = i & 63;
            int row = r0 + r;
            As[r][k] = (row < Nn) ? Asl[(size_t)row * HF + kb + k] : 0.f;
        }
        #pragma unroll 4
        for (int i = tid; i < 64 * 64; i += 256) {
            int k = i >> 6, c = i & 63;
            Bs[k][c] = g_WgT[(kb + k) * Cc + c];
        }
        __syncthreads();
        #pragma unroll
        for (int k = 0; k < 64; ++k) {
            float a[4];
            #pragma unroll
            for (int i = 0; i < 4; ++i) a[i] = As[ty * 4 + i][k];
            float4 b4 = *(const float4*)&Bs[k][tx * 4];
            float b[4] = {b4.x, b4.y, b4.z, b4.w};
            #pragma unroll
            for (int i = 0; i < 4; ++i)
                #pragma unroll
                for (int j = 0; j < 4; ++j)
                    acc[i][j] = fmaf(a[i], b[j], acc[i][j]);
        }
        __syncthreads();
    }
    #pragma unroll
    for (int i = 0; i < 4; ++i) {
        int row = r0 + ty * 4 + i;
        if (row >= Nn) continue;
        #pragma unroll
        for (int j = 0; j < 4; ++j) {
            int col = tx * 4 + j;
            size_t oidx = ((size_t)s * Nn + row) * Cc + col;
            Cm[oidx] = ALPHAc * resid[oidx] + (1.f - ALPHAc) * (acc[i][j] + bias[col]);
        }
    }
}

// ---------------- final: out[b,o,n,t] = bm[o] + Wm @ [x; h1; h2] ----------------
__global__ void final_out(const float* __restrict__ xT,
                          const float* __restrict__ h1,
                          const float* __restrict__ h2,
                          const float* __restrict__ bm,
                          float* __restrict__ out) {
    __shared__ float sX[16][64], sH1[16][64], sH2[16][64];
    const int s = blockIdx.x;
    const int n0 = blockIdx.y * 16;
    const int tid = threadIdx.x;
    for (int i = tid; i < 16 * 64; i += 256) {
        int nl = i >> 6, c = i & 63;
        int n = n0 + nl;
        size_t idx = ((size_t)s * Nn + (n < Nn ? n : 0)) * Cc + c;
        sX[nl][c]  = (n < Nn) ? xT[idx] : 0.f;
        sH1[nl][c] = (n < Nn) ? h1[idx] : 0.f;
        sH2[nl][c] = (n < Nn) ? h2[idx] : 0.f;
    }
    __syncthreads();
    const int o = tid & 63, ng = tid >> 6;
    float acc[4] = {0.f, 0.f, 0.f, 0.f};
    #pragma unroll 4
    for (int c = 0; c < 64; ++c) {
        float w0 = g_WmT[c * Cc + o];
        float w1 = g_WmT[(64 + c) * Cc + o];
        float w2 = g_WmT[(128 + c) * Cc + o];
        #pragma unroll
        for (int r = 0; r < 4; ++r) {
            int nl = ng + r * 4;
            acc[r] = fmaf(w0, sX[nl][c], fmaf(w1, sH1[nl][c], fmaf(w2, sH2[nl][c], acc[r])));
        }
    }
    const int b = s / Tt, t = s % Tt;
    const float bias = bm[o];
    #pragma unroll
    for (int r = 0; r < 4; ++r) {
        int n = n0 + ng + r * 4;
        if (n < Nn)
            out[(((size_t)b * Cc + o) * Nn + n) * Tt + t] = acc[r] + bias;
    }
}

// ---------------- launch ----------------
extern "C" void kernel_launch(void* const* d_in, const int* in_sizes, int n_in,
                              void* d_out, int out_size) {
    const float* x   = (const float*)d_in[0];
    const float* adj = (const float*)d_in[1];
    const float* W   = (const float*)d_in[2];
    const float* a1  = (const float*)d_in[3];
    const float* a2  = (const float*)d_in[4];
    const float* Wg  = (const float*)d_in[5];
    const float* bg  = (const float*)d_in[6];
    const float* Wm  = (const float*)d_in[7];
    const float* bm  = (const float*)d_in[8];
    float* out = (float*)d_out;

    float *xT, *h1T, *h2T, *hpr;
    cudaGetSymbolAddress((void**)&xT,  g_xT);
    cudaGetSymbolAddress((void**)&h1T, g_h1T);
    cudaGetSymbolAddress((void**)&h2T, g_h2T);
    cudaGetSymbolAddress((void**)&hpr, g_hpr);

    build_nbr<<<125, 128>>>(adj);
    prep_weights<<<64, 256>>>(W, Wg, Wm);
    transpose_in<<<dim3(32, 4, Bb), 192>>>(x, xT);

    const float* hin = xT;
    float* hb[2] = {h1T, h2T};
    for (int it = 0; it < 2; ++it) {
        gemm_proj<<<dim3(Ss, 8, Hh), 256>>>(hin, a1, a2);
        attn_agg<<<dim3(Nn, Ss), 128>>>(hpr);
        gemm_mix<<<dim3(Ss, 8), 256>>>(hpr, bg, xT, hb[it]);
        hin = hb[it];
    }
    final_out<<<dim3(Ss, (Nn + 15) / 16), 256>>>(xT, h1T, h2T, bm, out);
}